// round 7
// baseline (speedup 1.0000x reference)
#include <cuda_runtime.h>
#include <math.h>
#include <stdint.h>

#define BB   256   // batch
#define TT   512   // seq len
#define DD   64    // input size
#define HH   256   // hidden
#define G4H  1024  // 4*H

// ---------------- static device scratch (no runtime allocations) ----------------
__device__ float g_xw[(size_t)TT * BB * G4H];   // input projections (reused per layer)
__device__ float g_out0[(size_t)TT * BB * HH];  // layer-0 outputs
__device__ float g_hfin[BB * HH];               // final hidden state of layer 1

// ---------------- input projection GEMM (validated in round 2) ----------------
// g_xw[m][n] = sum_k in[m][k] * W[n][k] + b1[n] + b2[n],  m = t*BB + b
// SRC==0: in = x, layout [b][t][d].  SRC==1: in = g_out0, row m contiguous.
template<int K, int SRC>
__global__ __launch_bounds__(256)
void proj_kernel(const float* __restrict__ in,
                 const float* __restrict__ W,
                 const float* __restrict__ b1,
                 const float* __restrict__ b2)
{
    __shared__ float As[32][65];
    __shared__ float Ws[128][65];

    const int m0  = blockIdx.x * 32;
    const int n0  = blockIdx.y * 128;
    const int tid = threadIdx.x;        // 256 threads
    const int nn  = tid & 31;
    const int mg  = tid >> 5;           // 0..7

    float acc[4][4];
    #pragma unroll
    for (int i = 0; i < 4; i++)
        #pragma unroll
        for (int j = 0; j < 4; j++) acc[i][j] = 0.0f;

    for (int k0 = 0; k0 < K; k0 += 64) {
        for (int idx = tid; idx < 32 * 16; idx += 256) {
            int r  = idx >> 4;
            int kq = idx & 15;
            int m  = m0 + r;
            const float* src;
            if (SRC == 0) {
                int b = m & (BB - 1);
                int t = m >> 8;
                src = in + (size_t)(b * TT + t) * DD;
            } else {
                src = g_out0 + (size_t)m * K;
            }
            float4 v = *(const float4*)(src + k0 + kq * 4);
            As[r][kq * 4 + 0] = v.x;
            As[r][kq * 4 + 1] = v.y;
            As[r][kq * 4 + 2] = v.z;
            As[r][kq * 4 + 3] = v.w;
        }
        for (int idx = tid; idx < 128 * 16; idx += 256) {
            int r  = idx >> 4;
            int kq = idx & 15;
            float4 v = *(const float4*)(W + (size_t)(n0 + r) * K + k0 + kq * 4);
            Ws[r][kq * 4 + 0] = v.x;
            Ws[r][kq * 4 + 1] = v.y;
            Ws[r][kq * 4 + 2] = v.z;
            Ws[r][kq * 4 + 3] = v.w;
        }
        __syncthreads();

        #pragma unroll 16
        for (int kk = 0; kk < 64; kk++) {
            float a[4], w[4];
            #pragma unroll
            for (int i = 0; i < 4; i++) a[i] = As[mg * 4 + i][kk];
            #pragma unroll
            for (int i = 0; i < 4; i++) w[i] = Ws[nn + 32 * i][kk];
            #pragma unroll
            for (int i = 0; i < 4; i++)
                #pragma unroll
                for (int j = 0; j < 4; j++)
                    acc[i][j] += a[i] * w[j];
        }
        __syncthreads();
    }

    #pragma unroll
    for (int i = 0; i < 4; i++) {
        int m = m0 + mg * 4 + i;
        #pragma unroll
        for (int j = 0; j < 4; j++) {
            int n = n0 + nn + 32 * j;
            g_xw[(size_t)m * G4H + n] = acc[i][j] + b1[n] + b2[n];
        }
    }
}

// ---------------- persistent cluster-based LSTM layer ----------------
// Grid (8, 16): x = j-tile (cluster of 8), y = b-tile (16 independent clusters).
// 256 threads: thread = (cg = tid&31 -> j within tile, bq = tid>>5 -> batch pair).
// Whh slice (4 gates x 32 j x 256 k = 128 KB) lives in smem for all 512 steps.
// c-state lives in registers. h exchanged via DSMEM multicast stores + cluster.sync.
#define WS_STRIDE 260                       // 256 + pad (16B-aligned rows, bank spread)
#define HS_STRIDE 264
#define WS_FLOATS (128 * WS_STRIDE)         // 33280
#define HS_FLOATS (2 * 16 * HS_STRIDE)      // 8448
#define LSTM_SMEM_BYTES ((WS_FLOATS + HS_FLOATS) * 4)   // 166,912 B

// inline dot-accumulate (NOT a macro: macro param `w` collided with float4::w)
__device__ __forceinline__ void dot4(float& acc, const float4& wv, const float4& hv) {
    acc += wv.x * hv.x;
    acc += wv.y * hv.y;
    acc += wv.z * hv.z;
    acc += wv.w * hv.w;
}

__global__ __cluster_dims__(8, 1, 1) __launch_bounds__(256, 1)
void lstm_layer_kernel(const float* __restrict__ Whh, int write_out0)
{
    extern __shared__ float smem[];
    float* Ws = smem;                    // [128][WS_STRIDE]  col = g*32+cg
    float* Hs = smem + WS_FLOATS;        // [2][16][HS_STRIDE] (double buffered)

    const int tid = threadIdx.x;
    const int cg  = tid & 31;            // j within tile
    const int bq  = tid >> 5;            // 0..7, == warp id (uniform per warp)
    const int by  = blockIdx.x;          // j-tile == cluster rank
    const int bx  = blockIdx.y;          // b-tile
    const int j0  = by * 32;
    const int jg  = j0 + cg;             // global hidden index this thread owns
    const int b0  = bx * 16;
    const int bl0 = bq * 2;              // local batch base (2 batches per thread)

    // Load Whh slice into smem: col c = g*32+cg2  <-  Whh row g*HH + j0 + cg2
    for (int idx = tid; idx < 128 * 64; idx += 256) {
        int c   = idx >> 6;
        int kq  = idx & 63;
        int row = (c >> 5) * HH + j0 + (c & 31);
        float4 v = *(const float4*)(Whh + (size_t)row * HH + kq * 4);
        *(float4*)(Ws + c * WS_STRIDE + kq * 4) = v;
    }
    // Zero Hs buffer 0 (local reads only; remote writes fill buffer 1 first)
    for (int idx = tid; idx < 16 * HS_STRIDE; idx += 256)
        Hs[idx] = 0.0f;
    __syncthreads();

    // Precompute remote Hs base addresses for all 8 cluster ranks
    uint32_t hs_local;
    asm("{ .reg .u64 t; cvta.to.shared.u64 t, %1; cvt.u32.u64 %0, t; }"
        : "=r"(hs_local) : "l"(Hs));
    uint32_t peer[8];
    #pragma unroll
    for (int p = 0; p < 8; p++)
        asm("mapa.shared::cluster.u32 %0, %1, %2;"
            : "=r"(peer[p]) : "r"(hs_local), "r"(p));

    float creg[2] = {0.0f, 0.0f};

    // Align all CTAs before the recurrence
    asm volatile("barrier.cluster.arrive.aligned;" ::: "memory");
    asm volatile("barrier.cluster.wait.aligned;"   ::: "memory");

    for (int t = 0; t < TT; t++) {
        // Prefetch xw for this step (independent of h -> hides DRAM latency)
        const float* xw_t = g_xw + ((size_t)t * BB + b0) * G4H;
        float xw[2][4];
        #pragma unroll
        for (int bi = 0; bi < 2; bi++)
            #pragma unroll
            for (int g = 0; g < 4; g++)
                xw[bi][g] = __ldg(xw_t + (size_t)(bl0 + bi) * G4H + g * HH + jg);

        const float* HsR = Hs + (t & 1) * 16 * HS_STRIDE;
        const float* w0p = Ws + (0 * 32 + cg) * WS_STRIDE;
        const float* w1p = Ws + (1 * 32 + cg) * WS_STRIDE;
        const float* w2p = Ws + (2 * 32 + cg) * WS_STRIDE;
        const float* w3p = Ws + (3 * 32 + cg) * WS_STRIDE;
        const float* h0p = HsR + (bl0 + 0) * HS_STRIDE;
        const float* h1p = HsR + (bl0 + 1) * HS_STRIDE;

        float a00 = 0.f, a01 = 0.f, a10 = 0.f, a11 = 0.f;
        float a20 = 0.f, a21 = 0.f, a30 = 0.f, a31 = 0.f;

        #pragma unroll 2
        for (int k = 0; k < HH; k += 4) {
            float4 w0 = *(const float4*)(w0p + k);
            float4 w1 = *(const float4*)(w1p + k);
            float4 w2 = *(const float4*)(w2p + k);
            float4 w3 = *(const float4*)(w3p + k);
            float4 h0 = *(const float4*)(h0p + k);   // warp-uniform -> broadcast
            float4 h1 = *(const float4*)(h1p + k);
            dot4(a00, w0, h0); dot4(a01, w0, h1);
            dot4(a10, w1, h0); dot4(a11, w1, h1);
            dot4(a20, w2, h0); dot4(a21, w2, h1);
            dot4(a30, w3, h0); dot4(a31, w3, h1);
        }

        const int nb = (t + 1) & 1;
        float accg[4][2] = {{a00, a01}, {a10, a11}, {a20, a21}, {a30, a31}};

        #pragma unroll
        for (int bi = 0; bi < 2; bi++) {
            float zi = accg[0][bi] + xw[bi][0];
            float zf = accg[1][bi] + xw[bi][1];
            float zg = accg[2][bi] + xw[bi][2];
            float zo = accg[3][bi] + xw[bi][3];

            float ig = 1.0f / (1.0f + __expf(-zi));
            float fg = 1.0f / (1.0f + __expf(-zf));
            float gg = tanhf(zg);
            float og = 1.0f / (1.0f + __expf(-zo));

            float cn = fg * creg[bi] + ig * gg;
            float hn = og * tanhf(cn);
            creg[bi] = cn;

            // Multicast h into next-step buffer of all 8 peer CTAs (incl. self)
            uint32_t off = (uint32_t)(((nb * 16 + (bl0 + bi)) * HS_STRIDE + jg) * 4);
            #pragma unroll
            for (int p = 0; p < 8; p++)
                asm volatile("st.shared::cluster.f32 [%0], %1;"
                             :: "r"(peer[p] + off), "f"(hn) : "memory");

            if (write_out0)
                g_out0[((size_t)t * BB + (b0 + bl0 + bi)) * HH + jg] = hn;
            else if (t == TT - 1)
                g_hfin[(b0 + bl0 + bi) * HH + jg] = hn;
        }

        // Release our DSMEM stores / acquire peers' (arrive=release, wait=acquire)
        asm volatile("barrier.cluster.arrive.aligned;" ::: "memory");
        asm volatile("barrier.cluster.wait.aligned;"   ::: "memory");
    }
}

// ---------------- final linear: out[b] = dot(h_last[b], Wf) + bf ----------------
__global__ __launch_bounds__(256)
void final_kernel(const float* __restrict__ Wf, const float* __restrict__ bf,
                  float* __restrict__ out)
{
    int warp = (blockIdx.x * blockDim.x + threadIdx.x) >> 5;
    int lane = threadIdx.x & 31;
    if (warp >= BB) return;
    const float* h = g_hfin + warp * HH;
    float s = 0.0f;
    for (int k = lane; k < HH; k += 32) s += h[k] * Wf[k];
    #pragma unroll
    for (int o = 16; o > 0; o >>= 1) s += __shfl_xor_sync(0xffffffffu, s, o);
    if (lane == 0) out[warp] = s + bf[0];
}

// ---------------- launch: 5 graph nodes total ----------------
extern "C" void kernel_launch(void* const* d_in, const int* in_sizes, int n_in,
                              void* d_out, int out_size)
{
    const float* x    = (const float*)d_in[0];
    const float* Wih0 = (const float*)d_in[1];
    const float* Whh0 = (const float*)d_in[2];
    const float* bih0 = (const float*)d_in[3];
    const float* bhh0 = (const float*)d_in[4];
    const float* Wih1 = (const float*)d_in[5];
    const float* Whh1 = (const float*)d_in[6];
    const float* bih1 = (const float*)d_in[7];
    const float* bhh1 = (const float*)d_in[8];
    const float* Wf   = (const float*)d_in[9];
    const float* bf   = (const float*)d_in[10];
    float* out = (float*)d_out;

    cudaFuncSetAttribute(lstm_layer_kernel,
                         cudaFuncAttributeMaxDynamicSharedMemorySize,
                         LSTM_SMEM_BYTES);

    const dim3 proj_grid(TT * BB / 32, G4H / 128);   // (4096, 8)
    const dim3 lstm_grid(8, 16);                     // 16 clusters of 8 CTAs

    proj_kernel<DD, 0><<<proj_grid, 256>>>(x, Wih0, bih0, bhh0);
    lstm_layer_kernel<<<lstm_grid, 256, LSTM_SMEM_BYTES>>>(Whh0, 1);

    proj_kernel<HH, 1><<<proj_grid, 256>>>(nullptr, Wih1, bih1, bhh1);
    lstm_layer_kernel<<<lstm_grid, 256, LSTM_SMEM_BYTES>>>(Whh1, 0);

    final_kernel<<<(BB * 32 + 255) / 256, 256>>>(Wf, bf, out);
}

// round 8
// speedup vs baseline: 1.0290x; 1.0290x over previous
#include <cuda_runtime.h>
#include <math.h>
#include <stdint.h>

#define BB   256   // batch
#define TT   512   // seq len
#define DD   64    // input size
#define HH   256   // hidden
#define G4H  1024  // 4*H

// ---------------- static device scratch (no runtime allocations) ----------------
__device__ float g_xw[(size_t)TT * BB * G4H];   // input projections (reused per layer)
__device__ float g_out0[(size_t)TT * BB * HH];  // layer-0 outputs
__device__ float g_hfin[BB * HH];               // final hidden state of layer 1

// ---------------- input projection GEMM (validated) ----------------
template<int K, int SRC>
__global__ __launch_bounds__(256)
void proj_kernel(const float* __restrict__ in,
                 const float* __restrict__ W,
                 const float* __restrict__ b1,
                 const float* __restrict__ b2)
{
    __shared__ float As[32][65];
    __shared__ float Ws[128][65];

    const int m0  = blockIdx.x * 32;
    const int n0  = blockIdx.y * 128;
    const int tid = threadIdx.x;        // 256 threads
    const int nn  = tid & 31;
    const int mg  = tid >> 5;           // 0..7

    float acc[4][4];
    #pragma unroll
    for (int i = 0; i < 4; i++)
        #pragma unroll
        for (int j = 0; j < 4; j++) acc[i][j] = 0.0f;

    for (int k0 = 0; k0 < K; k0 += 64) {
        for (int idx = tid; idx < 32 * 16; idx += 256) {
            int r  = idx >> 4;
            int kq = idx & 15;
            int m  = m0 + r;
            const float* src;
            if (SRC == 0) {
                int b = m & (BB - 1);
                int t = m >> 8;
                src = in + (size_t)(b * TT + t) * DD;
            } else {
                src = g_out0 + (size_t)m * K;
            }
            float4 v = *(const float4*)(src + k0 + kq * 4);
            As[r][kq * 4 + 0] = v.x;
            As[r][kq * 4 + 1] = v.y;
            As[r][kq * 4 + 2] = v.z;
            As[r][kq * 4 + 3] = v.w;
        }
        for (int idx = tid; idx < 128 * 16; idx += 256) {
            int r  = idx >> 4;
            int kq = idx & 15;
            float4 v = *(const float4*)(W + (size_t)(n0 + r) * K + k0 + kq * 4);
            Ws[r][kq * 4 + 0] = v.x;
            Ws[r][kq * 4 + 1] = v.y;
            Ws[r][kq * 4 + 2] = v.z;
            Ws[r][kq * 4 + 3] = v.w;
        }
        __syncthreads();

        #pragma unroll 16
        for (int kk = 0; kk < 64; kk++) {
            float a[4], w[4];
            #pragma unroll
            for (int i = 0; i < 4; i++) a[i] = As[mg * 4 + i][kk];
            #pragma unroll
            for (int i = 0; i < 4; i++) w[i] = Ws[nn + 32 * i][kk];
            #pragma unroll
            for (int i = 0; i < 4; i++)
                #pragma unroll
                for (int j = 0; j < 4; j++)
                    acc[i][j] += a[i] * w[j];
        }
        __syncthreads();
    }

    #pragma unroll
    for (int i = 0; i < 4; i++) {
        int m = m0 + mg * 4 + i;
        #pragma unroll
        for (int j = 0; j < 4; j++) {
            int n = n0 + nn + 32 * j;
            g_xw[(size_t)m * G4H + n] = acc[i][j] + b1[n] + b2[n];
        }
    }
}

// ---------------- fast MUFU-free math (fma/alu pipes only) ----------------
// exp(x) via range-reduced 2^f, degree-6 poly (rel err ~1.2e-7)
__device__ __forceinline__ float exp_fast(float x) {
    float y = x * 1.4426950408889634f;
    y = fminf(fmaxf(y, -126.0f), 126.0f);
    float t = y + 12582912.0f;                     // round-to-nearest magic (2^23*1.5)
    int   n = __float_as_int(t) - 0x4B400000;
    float f = y - (t - 12582912.0f);               // f in [-0.5, 0.5]
    float p = 1.5403530393381609e-4f;
    p = fmaf(p, f, 1.3333558146428443e-3f);
    p = fmaf(p, f, 9.6181291076284772e-3f);
    p = fmaf(p, f, 5.5504108664821580e-2f);
    p = fmaf(p, f, 2.4022650695910071e-1f);
    p = fmaf(p, f, 6.9314718055994531e-1f);
    p = fmaf(p, f, 1.0f);
    float s = __int_as_float((n + 127) << 23);
    return p * s;
}

// 1/d for d > 0: bit-trick seed + 3 Newton iterations (rel err ~1e-10)
__device__ __forceinline__ float rcp_fast(float d) {
    float x = __int_as_float(0x7EF311C3 - __float_as_int(d));
    float r;
    r = fmaf(-d, x, 1.0f); x = fmaf(x, r, x);
    r = fmaf(-d, x, 1.0f); x = fmaf(x, r, x);
    r = fmaf(-d, x, 1.0f); x = fmaf(x, r, x);
    return x;
}

__device__ __forceinline__ float sigmoid_fast(float z) {
    return rcp_fast(1.0f + exp_fast(-z));
}
__device__ __forceinline__ float tanh_fast(float z) {
    float u = exp_fast(-2.0f * z);
    return (1.0f - u) * rcp_fast(1.0f + u);
}

// packed f32x2 FMA (Blackwell FFMA2; PTX-only)
__device__ __forceinline__ void ffma2(double& acc, double a, double b) {
    asm("fma.rn.f32x2 %0, %1, %2, %3;" : "=d"(acc) : "d"(a), "d"(b), "d"(acc));
}

// ---------------- persistent cluster-based LSTM layer ----------------
// Grid (8, 16): x = j-tile (cluster of 8), y = b-tile (16 independent clusters).
// GEMM mapping:     thread = (row r = g*32+jj in [0,128), batch-half bh in {0,1}),
//                   acc over 8 batches, full k=256, f32x2-packed over k-pairs.
//                   Ws read once per batch-half (2x crossbar traffic, was 8x).
// Epilogue mapping: thread = (jj = tid&31, batch-pair bq = tid>>5)  [round-7 proven].
// Whh slice (128 KB) smem-resident all 512 steps; c-state in registers;
// h exchanged via DSMEM multicast stores + one cluster barrier per step.
#define WS_STRIDE 260
#define HS_STRIDE 264
#define ZS_STRIDE 20
#define WS_FLOATS (128 * WS_STRIDE)         // 33280
#define HS_FLOATS (2 * 16 * HS_STRIDE)      // 8448
#define ZS_FLOATS (128 * ZS_STRIDE)         // 2560
#define LSTM_SMEM_BYTES ((WS_FLOATS + HS_FLOATS + ZS_FLOATS) * 4)   // 177,152 B

__global__ __cluster_dims__(8, 1, 1) __launch_bounds__(256, 1)
void lstm_layer_kernel(const float* __restrict__ Whh, int write_out0)
{
    extern __shared__ float smem[];
    float* Ws = smem;                          // [128][WS_STRIDE], row r = g*32+jj
    float* Hs = smem + WS_FLOATS;              // [2][16][HS_STRIDE]
    float* Zs = smem + WS_FLOATS + HS_FLOATS;  // [128][ZS_STRIDE]  (z gather)

    const int tid = threadIdx.x;
    // GEMM mapping
    const int r    = tid & 127;                // row = g*32 + jj
    const int bh8  = (tid >> 7) * 8;           // batch-half base (0 or 8)
    // epilogue mapping
    const int cg   = tid & 31;
    const int bq   = tid >> 5;
    const int bl0  = bq * 2;
    const int by   = blockIdx.x;               // j-tile == cluster rank
    const int bx   = blockIdx.y;               // b-tile
    const int j0   = by * 32;
    const int jg   = j0 + cg;
    const int b0   = bx * 16;

    // Stage Whh slice: col c = g*32+jj  <-  Whh row g*HH + j0 + jj
    for (int idx = tid; idx < 128 * 64; idx += 256) {
        int c   = idx >> 6;
        int kq  = idx & 63;
        int row = (c >> 5) * HH + j0 + (c & 31);
        float4 v = *(const float4*)(Whh + (size_t)row * HH + kq * 4);
        *(float4*)(Ws + c * WS_STRIDE + kq * 4) = v;
    }
    // Zero Hs buffer 0 (step 0 reads it; step 0 writes go to buffer 1)
    for (int idx = tid; idx < 16 * HS_STRIDE; idx += 256)
        Hs[idx] = 0.0f;
    __syncthreads();

    // Remote Hs base addresses for all 8 cluster ranks
    uint32_t hs_local;
    asm("{ .reg .u64 t; cvta.to.shared.u64 t, %1; cvt.u32.u64 %0, t; }"
        : "=r"(hs_local) : "l"(Hs));
    uint32_t peer[8];
    #pragma unroll
    for (int p = 0; p < 8; p++)
        asm("mapa.shared::cluster.u32 %0, %1, %2;"
            : "=r"(peer[p]) : "r"(hs_local), "r"(p));

    float creg[2] = {0.0f, 0.0f};

    asm volatile("barrier.cluster.arrive.aligned;" ::: "memory");
    asm volatile("barrier.cluster.wait.aligned;"   ::: "memory");

    const float* wrow = Ws + r * WS_STRIDE;

    for (int t = 0; t < TT; t++) {
        // Prefetch xw for this step's epilogue (coalesced, hides DRAM latency)
        const float* xw_t = g_xw + ((size_t)t * BB + b0) * G4H;
        float xwv[2][4];
        #pragma unroll
        for (int bi = 0; bi < 2; bi++)
            #pragma unroll
            for (int g = 0; g < 4; g++)
                xwv[bi][g] = __ldg(xw_t + (size_t)(bl0 + bi) * G4H + g * HH + jg);

        // ---- GEMM: z[r][b] partials, f32x2-packed over (even k, odd k) ----
        const float* HsR = Hs + (t & 1) * (16 * HS_STRIDE);
        double acc[8];
        #pragma unroll
        for (int b = 0; b < 8; b++) acc[b] = 0.0;

        #pragma unroll 4
        for (int k = 0; k < HH; k += 4) {
            double2 w = *(const double2*)(wrow + k);
            #pragma unroll
            for (int b = 0; b < 8; b++) {
                double2 h = *(const double2*)(HsR + (bh8 + b) * HS_STRIDE + k);
                ffma2(acc[b], w.x, h.x);
                ffma2(acc[b], w.y, h.y);
            }
        }

        // Reduce packed halves and store z to Zs[r][bh8..bh8+7]
        float z[8];
        #pragma unroll
        for (int b = 0; b < 8; b++)
            z[b] = __int_as_float(__double2loint(acc[b])) +
                   __int_as_float(__double2hiint(acc[b]));
        {
            float4 v0 = make_float4(z[0], z[1], z[2], z[3]);
            float4 v1 = make_float4(z[4], z[5], z[6], z[7]);
            *(float4*)(Zs + r * ZS_STRIDE + bh8)     = v0;
            *(float4*)(Zs + r * ZS_STRIDE + bh8 + 4) = v1;
        }
        __syncthreads();

        // ---- epilogue: gates, c/h update, DSMEM multicast ----
        const int nb = (t + 1) & 1;
        #pragma unroll
        for (int bi = 0; bi < 2; bi++) {
            int b = bl0 + bi;
            float zi = Zs[(0 * 32 + cg) * ZS_STRIDE + b] + xwv[bi][0];
            float zf = Zs[(1 * 32 + cg) * ZS_STRIDE + b] + xwv[bi][1];
            float zg = Zs[(2 * 32 + cg) * ZS_STRIDE + b] + xwv[bi][2];
            float zo = Zs[(3 * 32 + cg) * ZS_STRIDE + b] + xwv[bi][3];

            float ig = sigmoid_fast(zi);
            float fg = sigmoid_fast(zf);
            float gg = tanh_fast(zg);
            float og = sigmoid_fast(zo);

            float cn = fmaf(fg, creg[bi], ig * gg);
            float hn = og * tanh_fast(cn);
            creg[bi] = cn;

            // Multicast h into next-step buffer of all 8 cluster CTAs
            uint32_t off = (uint32_t)(((nb * 16 + b) * HS_STRIDE + jg) * 4);
            #pragma unroll
            for (int p = 0; p < 8; p++)
                asm volatile("st.shared::cluster.f32 [%0], %1;"
                             :: "r"(peer[p] + off), "f"(hn) : "memory");

            if (write_out0)
                g_out0[((size_t)t * BB + (b0 + b)) * HH + jg] = hn;
            else if (t == TT - 1)
                g_hfin[(b0 + b) * HH + jg] = hn;
        }

        // One cluster barrier per step: orders DSMEM h-writes before next reads,
        // and doubles as the CTA-wide sync protecting Zs reuse.
        asm volatile("barrier.cluster.arrive.aligned;" ::: "memory");
        asm volatile("barrier.cluster.wait.aligned;"   ::: "memory");
    }
}

// ---------------- final linear: out[b] = dot(h_last[b], Wf) + bf ----------------
__global__ __launch_bounds__(256)
void final_kernel(const float* __restrict__ Wf, const float* __restrict__ bf,
                  float* __restrict__ out)
{
    int warp = (blockIdx.x * blockDim.x + threadIdx.x) >> 5;
    int lane = threadIdx.x & 31;
    if (warp >= BB) return;
    const float* h = g_hfin + warp * HH;
    float s = 0.0f;
    for (int k = lane; k < HH; k += 32) s += h[k] * Wf[k];
    #pragma unroll
    for (int o = 16; o > 0; o >>= 1) s += __shfl_xor_sync(0xffffffffu, s, o);
    if (lane == 0) out[warp] = s + bf[0];
}

// ---------------- launch: 5 graph nodes total ----------------
extern "C" void kernel_launch(void* const* d_in, const int* in_sizes, int n_in,
                              void* d_out, int out_size)
{
    const float* x    = (const float*)d_in[0];
    const float* Wih0 = (const float*)d_in[1];
    const float* Whh0 = (const float*)d_in[2];
    const float* bih0 = (const float*)d_in[3];
    const float* bhh0 = (const float*)d_in[4];
    const float* Wih1 = (const float*)d_in[5];
    const float* Whh1 = (const float*)d_in[6];
    const float* bih1 = (const float*)d_in[7];
    const float* bhh1 = (const float*)d_in[8];
    const float* Wf   = (const float*)d_in[9];
    const float* bf   = (const float*)d_in[10];
    float* out = (float*)d_out;

    cudaFuncSetAttribute(lstm_layer_kernel,
                         cudaFuncAttributeMaxDynamicSharedMemorySize,
                         LSTM_SMEM_BYTES);

    const dim3 proj_grid(TT * BB / 32, G4H / 128);   // (4096, 8)
    const dim3 lstm_grid(8, 16);                     // 16 clusters of 8 CTAs

    proj_kernel<DD, 0><<<proj_grid, 256>>>(x, Wih0, bih0, bhh0);
    lstm_layer_kernel<<<lstm_grid, 256, LSTM_SMEM_BYTES>>>(Whh0, 1);

    proj_kernel<HH, 1><<<proj_grid, 256>>>(nullptr, Wih1, bih1, bhh1);
    lstm_layer_kernel<<<lstm_grid, 256, LSTM_SMEM_BYTES>>>(Whh1, 0);

    final_kernel<<<(BB * 32 + 255) / 256, 256>>>(Wf, bf, out);
}